// round 4
// baseline (speedup 1.0000x reference)
#include <cuda_runtime.h>
#include <cuda_bf16.h>
#include <math.h>

// ---------------------------------------------------------------------------
// GCN_Protein: 3x GCNConv(sym-norm, self-loops) -> mean pool -> MLP -> log_softmax
//   - Dtype-robust index loads: edge_index/batch may be int32 (JAX x64 off)
//     or int64; a device-side detector samples odd words and sets flags.
//   - CSR-by-dst + warp-per-node SpMM (register accumulation, no hot atomics).
//   - A(hW) = (Ah)W reassociation: SpMM at the narrow width per layer.
//   - fp32 shared-tiled FFMA GEMM, fused bias+relu epilogues.
//   - No host CUDA API except kernel launches (graph-capture safe).
// ---------------------------------------------------------------------------

#define NN 100000
#define NE 1600000
#define NTOT (NN + NE)
#define NG 512
#define OUTF 10

// ------------------------- scratch (device globals) ------------------------
__device__ int   g_e64;            // 1 if edge_index is int64, else int32
__device__ int   g_b64;            // 1 if batch is int64, else int32
__device__ int   g_deg[NN];
__device__ int   g_rowptr[NN + 1];
__device__ int   g_cursor[NN];
__device__ float g_dinv[NN];
__device__ int   g_col[NTOT];
__device__ float g_wgt[NTOT];
__device__ float g_bufA[(size_t)NN * 64];
__device__ float g_bufB[(size_t)NN * 64];
__device__ float g_bufC[(size_t)NN * 128];
__device__ float g_bufD[(size_t)NN * 128];
__device__ float g_pool[NG * 128];
__device__ float g_cnt[NG];

template <int ID>
__device__ __forceinline__ float* scratch() {
    if (ID == 0) return g_bufA;
    if (ID == 1) return g_bufB;
    if (ID == 2) return g_bufC;
    return g_bufD;
}

__device__ __forceinline__ int clampi(int v, int hi) {
    return v < 0 ? 0 : (v >= hi ? hi - 1 : v);
}

// Load element i of an index buffer that is either int32 or int64 (values are
// small non-negative, so the low word suffices for int64).
__device__ __forceinline__ int load_idx(const int* __restrict__ p, int i, int is64) {
    return is64 ? p[2 * i] : p[i];
}

// ------------------------------ dtype detection ------------------------------
// For int64 data (all values < 2^31, non-negative), every odd 32-bit word is a
// zero high-half. For int32 data odd words are live values. Sample only within
// the minimum footprint valid under BOTH interpretations.
__global__ void k_detect(const int* __restrict__ ei, const int* __restrict__ batch) {
    __shared__ int nz_e, nz_b;
    int t = threadIdx.x;                       // 128 threads
    if (t == 0) { nz_e = 0; nz_b = 0; }
    __syncthreads();
    // edges: odd words in [0, 2*NE) (int32 buffer has 2*NE words minimum)
    long long stride = (2LL * NE) / 128;
    int we = (int)((long long)t * stride) | 1;
    if (ei[we] != 0) atomicAdd(&nz_e, 1);
    // batch: odd words near the END of [0, NN) (sorted -> values ~511 there)
    int wb = (NN - 1 - 2 * t) | 1;
    if (batch[wb] != 0) atomicAdd(&nz_b, 1);
    __syncthreads();
    if (t == 0) { g_e64 = (nz_e == 0); g_b64 = (nz_b == 0); }
}

// ------------------------------ preprocessing ------------------------------
__global__ void k_init() {
    int i = blockIdx.x * blockDim.x + threadIdx.x;
    if (i < NN) { g_deg[i] = 1; g_cursor[i] = 0; }   // self-loop contributes 1
    if (i < NG * 128) g_pool[i] = 0.f;
    if (i < NG) g_cnt[i] = 0.f;
}

__global__ void k_count(const int* __restrict__ ei) {
    int e = blockIdx.x * blockDim.x + threadIdx.x;
    if (e < NE) {
        int d = clampi(load_idx(ei, NE + e, g_e64), NN);
        atomicAdd(&g_deg[d], 1);
    }
}

// Single-block exclusive scan over g_deg -> g_rowptr, plus dinv = rsqrt(deg).
__global__ void k_scan() {
    __shared__ int ssum[1024];
    int tid = threadIdx.x;
    const int CH = (NN + 1023) / 1024;     // 98
    int s = tid * CH;
    int e = s + CH; if (e > NN) e = NN;
    int loc = 0;
    for (int i = s; i < e; i++) loc += g_deg[i];
    ssum[tid] = loc;
    __syncthreads();
    for (int off = 1; off < 1024; off <<= 1) {
        int v = (tid >= off) ? ssum[tid - off] : 0;
        __syncthreads();
        ssum[tid] += v;
        __syncthreads();
    }
    int run = (tid == 0) ? 0 : ssum[tid - 1];
    for (int i = s; i < e; i++) {
        g_rowptr[i] = run;
        int d = g_deg[i];
        run += d;
        g_dinv[i] = rsqrtf((float)d);
    }
    if (tid == 1023) g_rowptr[NN] = ssum[1023];
}

__global__ void k_fill(const int* __restrict__ ei) {
    int idx = blockIdx.x * blockDim.x + threadIdx.x;
    if (idx < NN) {
        int pos = g_rowptr[idx] + atomicAdd(&g_cursor[idx], 1);
        float di = g_dinv[idx];
        g_col[pos] = idx;
        g_wgt[pos] = di * di;
    } else if (idx < NTOT) {
        int e = idx - NN;
        int is64 = g_e64;
        int s = clampi(load_idx(ei, e, is64), NN);
        int d = clampi(load_idx(ei, NE + e, is64), NN);
        int pos = g_rowptr[d] + atomicAdd(&g_cursor[d], 1);
        g_col[pos] = s;
        g_wgt[pos] = g_dinv[s] * g_dinv[d];
    }
}

// ---------------------------------- SpMM -----------------------------------
// warp-per-node: out[n] = sum_k wgt[k] * hin[col[k]]; optional (+bias, relu).
template <int F, bool EPI, int IN, int OUT>
__global__ void k_spmm(const float* __restrict__ bias) {
    const float* __restrict__ hin  = scratch<IN>();
    float*       __restrict__ hout = scratch<OUT>();
    constexpr int VEC = F / 32;   // 2 or 4 floats per lane
    int warp = (blockIdx.x * blockDim.x + threadIdx.x) >> 5;
    int lane = threadIdx.x & 31;
    if (warp >= NN) return;
    int beg = g_rowptr[warp], end = g_rowptr[warp + 1];
    float acc[VEC];
#pragma unroll
    for (int v = 0; v < VEC; v++) acc[v] = 0.f;

    for (int k = beg; k < end; k++) {
        int   c  = g_col[k];
        float wt = g_wgt[k];
        const float* p = hin + (size_t)c * F + lane * VEC;
        if (VEC == 4) {
            float4 v = *(const float4*)p;
            acc[0] += wt * v.x; acc[1] += wt * v.y;
            acc[2] += wt * v.z; acc[3] += wt * v.w;
        } else {
            float2 v = *(const float2*)p;
            acc[0] += wt * v.x; acc[1] += wt * v.y;
        }
    }
    float* q = hout + (size_t)warp * F + lane * VEC;
    if (EPI) {
#pragma unroll
        for (int v = 0; v < VEC; v++) {
            acc[v] += bias[lane * VEC + v];
            acc[v] = fmaxf(acc[v], 0.f);
        }
    }
    if (VEC == 4) *(float4*)q = make_float4(acc[0], acc[1], acc[2], acc[3]);
    else          *(float2*)q = make_float2(acc[0], acc[1]);
}

// ---------------------------------- GEMM -----------------------------------
// C[N, BN] = A[N, K] @ W[K, BN] (+bias, relu if EPI). BM=64 rows/block, KT=64.
template <int K, int BN, bool EPI, int IN, int OUT>
__global__ void k_gemm(const float* __restrict__ Aext, const float* __restrict__ W,
                       const float* __restrict__ bias) {
    const float* __restrict__ A = (IN < 0) ? Aext : scratch<(IN < 0) ? 0 : IN>();
    float*       __restrict__ C = scratch<OUT>();
    constexpr int BM = 64, KT = 64;
    constexpr int TM = 4, TN = BN / 16;            // 4 or 8
    __shared__ float As[KT * BM];                  // transposed: As[k][m]
    __shared__ float Ws[KT * BN];                  // Ws[k][n]
    int tid = threadIdx.x;                         // 256 threads
    int tx = tid & 15;                             // n-dir
    int ty = tid >> 4;                             // m-dir
    int row0 = blockIdx.x * BM;

    float acc[TM][TN];
#pragma unroll
    for (int i = 0; i < TM; i++)
#pragma unroll
        for (int j = 0; j < TN; j++) acc[i][j] = 0.f;

    for (int kt = 0; kt < K; kt += KT) {
#pragma unroll
        for (int it = 0; it < (BM * KT / 4) / 256; it++) {
            int vi = tid + 256 * it;
            int m  = vi / (KT / 4);
            int kv = vi % (KT / 4);
            float4 v = make_float4(0.f, 0.f, 0.f, 0.f);
            int r = row0 + m;
            if (r < NN) v = *(const float4*)(A + (size_t)r * K + kt + kv * 4);
            As[(kv * 4 + 0) * BM + m] = v.x;
            As[(kv * 4 + 1) * BM + m] = v.y;
            As[(kv * 4 + 2) * BM + m] = v.z;
            As[(kv * 4 + 3) * BM + m] = v.w;
        }
#pragma unroll
        for (int it = 0; it < (KT * BN / 4) / 256; it++) {
            int vi = tid + 256 * it;
            int k  = vi / (BN / 4);
            int nv = vi % (BN / 4);
            *(float4*)&Ws[k * BN + nv * 4] =
                *(const float4*)(W + (size_t)(kt + k) * BN + nv * 4);
        }
        __syncthreads();
#pragma unroll
        for (int k = 0; k < KT; k++) {
            float4 av = *(const float4*)&As[k * BM + ty * TM];
            float a[TM] = {av.x, av.y, av.z, av.w};
            float w[TN];
#pragma unroll
            for (int jv = 0; jv < TN / 4; jv++) {
                float4 wv = *(const float4*)&Ws[k * BN + tx * TN + jv * 4];
                w[jv * 4 + 0] = wv.x; w[jv * 4 + 1] = wv.y;
                w[jv * 4 + 2] = wv.z; w[jv * 4 + 3] = wv.w;
            }
#pragma unroll
            for (int i = 0; i < TM; i++)
#pragma unroll
                for (int j = 0; j < TN; j++) acc[i][j] += a[i] * w[j];
        }
        __syncthreads();
    }
#pragma unroll
    for (int i = 0; i < TM; i++) {
        int r = row0 + ty * TM + i;
        if (r < NN) {
#pragma unroll
            for (int jv = 0; jv < TN / 4; jv++) {
                float4 v;
                float* pv = &acc[i][jv * 4];
                v.x = pv[0]; v.y = pv[1]; v.z = pv[2]; v.w = pv[3];
                if (EPI) {
                    int n = tx * TN + jv * 4;
                    v.x = fmaxf(v.x + bias[n + 0], 0.f);
                    v.y = fmaxf(v.y + bias[n + 1], 0.f);
                    v.z = fmaxf(v.z + bias[n + 2], 0.f);
                    v.w = fmaxf(v.w + bias[n + 3], 0.f);
                }
                *(float4*)(C + (size_t)r * BN + tx * TN + jv * 4) = v;
            }
        }
    }
}

// ------------------------------- mean pooling -------------------------------
// batch is sorted; accumulate in registers, flush on graph-boundary change.
__global__ void k_pool(const int* __restrict__ batch) {
    const float* __restrict__ h = g_bufC;
    constexpr int CH = 64;
    int n0 = blockIdx.x * CH;
    int t  = threadIdx.x;                 // 128 = feature
    if (n0 >= NN) return;
    int is64 = g_b64;
    int end = n0 + CH; if (end > NN) end = NN;
    float acc = 0.f, cacc = 0.f;
    int cur = clampi(load_idx(batch, n0, is64), NG);
    for (int n = n0; n < end; n++) {
        int g = clampi(load_idx(batch, n, is64), NG);
        if (g != cur) {
            atomicAdd(&g_pool[cur * 128 + t], acc);
            if (t == 0) atomicAdd(&g_cnt[cur], cacc);
            acc = 0.f; cacc = 0.f; cur = g;
        }
        acc  += h[(size_t)n * 128 + t];
        cacc += 1.f;
    }
    atomicAdd(&g_pool[cur * 128 + t], acc);
    if (t == 0) atomicAdd(&g_cnt[cur], cacc);
}

// --------------------------- classifier + log_softmax -----------------------
__global__ void k_cls(const float* __restrict__ Wc1, const float* __restrict__ bc1,
                      const float* __restrict__ Wc2, const float* __restrict__ bc2,
                      float* __restrict__ out) {
    int g = blockIdx.x;
    int t = threadIdx.x;                  // 128
    __shared__ float p[128];
    __shared__ float z[64];
    __shared__ float lo[OUTF];
    float c = fmaxf(g_cnt[g], 1.f);
    p[t] = g_pool[g * 128 + t] / c;
    __syncthreads();
    if (t < 64) {
        float a = bc1[t];
#pragma unroll 8
        for (int k = 0; k < 128; k++) a += p[k] * Wc1[k * 64 + t];
        z[t] = fmaxf(a, 0.f);
    }
    __syncthreads();
    if (t < OUTF) {
        float a = bc2[t];
#pragma unroll 8
        for (int k = 0; k < 64; k++) a += z[k] * Wc2[k * OUTF + t];
        lo[t] = a;
    }
    __syncthreads();
    if (t < OUTF) {
        float m = lo[0];
#pragma unroll
        for (int i = 1; i < OUTF; i++) m = fmaxf(m, lo[i]);
        float s = 0.f;
#pragma unroll
        for (int i = 0; i < OUTF; i++) s += expf(lo[i] - m);
        out[g * OUTF + t] = lo[t] - m - logf(s);
    }
}

// --------------------------------- launch -----------------------------------
extern "C" void kernel_launch(void* const* d_in, const int* in_sizes, int n_in,
                              void* d_out, int out_size) {
    const float* x     = (const float*)d_in[0];
    const int*   ei    = (const int*)d_in[1];     // int32 or int64 (detected)
    const int*   batch = (const int*)d_in[2];     // int32 or int64 (detected)
    const float* W1  = (const float*)d_in[3];
    const float* b1  = (const float*)d_in[4];
    const float* W2  = (const float*)d_in[5];
    const float* b2  = (const float*)d_in[6];
    const float* W3  = (const float*)d_in[7];
    const float* b3  = (const float*)d_in[8];
    const float* Wc1 = (const float*)d_in[9];
    const float* bc1 = (const float*)d_in[10];
    const float* Wc2 = (const float*)d_in[11];
    const float* bc2 = (const float*)d_in[12];
    float* out = (float*)d_out;

    const int GB = (NN + 63) / 64;          // gemm blocks
    const int SP = (NN + 3) / 4;            // spmm blocks (4 warps/block)

    k_detect<<<1, 128>>>(ei, batch);
    k_init  <<<(NN + 255) / 256, 256>>>();
    k_count <<<(NE + 255) / 256, 256>>>(ei);
    k_scan  <<<1, 1024>>>();
    k_fill  <<<(NTOT + 255) / 256, 256>>>(ei);

    // buffers: 0=A(64w) 1=B(64w) 2=C(128w) 3=D(128w)
    // L1: t0 = x @ W1 -> A ; h1 = relu(CSR·A + b1) -> B
    k_gemm<128, 64, false, -1, 0><<<GB, 256>>>(x, W1, nullptr);
    k_spmm<64, true, 0, 1>       <<<SP, 128>>>(b1);
    // L2: s2 = CSR·B -> A ; h2 = relu(A @ W2 + b2) -> C
    k_spmm<64, false, 1, 0>      <<<SP, 128>>>(nullptr);
    k_gemm<64, 128, true, 0, 2>  <<<GB, 256>>>(nullptr, W2, b2);
    // L3: t3 = C @ W3 -> D ; h3 = relu(CSR·D + b3) -> C
    k_gemm<128, 128, false, 2, 3><<<GB, 256>>>(nullptr, W3, nullptr);
    k_spmm<128, true, 3, 2>      <<<SP, 128>>>(b3);

    k_pool<<<(NN + 63) / 64, 128>>>(batch);
    k_cls <<<NG, 128>>>(Wc1, bc1, Wc2, bc2, out);
}

// round 5
// speedup vs baseline: 1.2890x; 1.2890x over previous
#include <cuda_runtime.h>
#include <cuda_bf16.h>
#include <math.h>

// ---------------------------------------------------------------------------
// GCN_Protein: 3x GCNConv(sym-norm, self-loops) -> mean pool -> MLP -> log_softmax
//   - Dtype-robust index loads (int32 or int64, device-detected).
//   - CSR-by-dst + warp-per-node SpMM (register accumulation, no hot atomics).
//   - A(hW) = (Ah)W reassociation: SpMM at the narrow width per layer.
//   - fp32 shared-tiled FFMA GEMM, fused bias+relu epilogues.
//   - R4: PARALLEL prefix scan (was a 160us single-block serial scan).
// ---------------------------------------------------------------------------

#define NN 100000
#define NE 1600000
#define NTOT (NN + NE)
#define NG 512
#define OUTF 10

#define SCAN_B 512
#define SCAN_NB ((NN + SCAN_B - 1) / SCAN_B)   // 196

// ------------------------- scratch (device globals) ------------------------
__device__ int   g_e64;            // 1 if edge_index is int64, else int32
__device__ int   g_b64;            // 1 if batch is int64, else int32
__device__ int   g_deg[NN];
__device__ int   g_rowptr[NN + 1];
__device__ int   g_cursor[NN];
__device__ float g_dinv[NN];
__device__ int   g_part[SCAN_NB];
__device__ int   g_partoff[SCAN_NB];
__device__ int   g_col[NTOT];
__device__ float g_wgt[NTOT];
__device__ float g_bufA[(size_t)NN * 64];
__device__ float g_bufB[(size_t)NN * 64];
__device__ float g_bufC[(size_t)NN * 128];
__device__ float g_bufD[(size_t)NN * 128];
__device__ float g_pool[NG * 128];
__device__ float g_cnt[NG];

template <int ID>
__device__ __forceinline__ float* scratch() {
    if (ID == 0) return g_bufA;
    if (ID == 1) return g_bufB;
    if (ID == 2) return g_bufC;
    return g_bufD;
}

__device__ __forceinline__ int clampi(int v, int hi) {
    return v < 0 ? 0 : (v >= hi ? hi - 1 : v);
}

__device__ __forceinline__ int load_idx(const int* __restrict__ p, int i, int is64) {
    return is64 ? p[2 * i] : p[i];
}

// ------------------------------ dtype detection ------------------------------
__global__ void k_detect(const int* __restrict__ ei, const int* __restrict__ batch) {
    __shared__ int nz_e, nz_b;
    int t = threadIdx.x;                       // 128 threads
    if (t == 0) { nz_e = 0; nz_b = 0; }
    __syncthreads();
    long long stride = (2LL * NE) / 128;
    int we = (int)((long long)t * stride) | 1;
    if (ei[we] != 0) atomicAdd(&nz_e, 1);
    int wb = (NN - 1 - 2 * t) | 1;
    if (batch[wb] != 0) atomicAdd(&nz_b, 1);
    __syncthreads();
    if (t == 0) { g_e64 = (nz_e == 0); g_b64 = (nz_b == 0); }
}

// ------------------------------ preprocessing ------------------------------
__global__ void k_init() {
    int i = blockIdx.x * blockDim.x + threadIdx.x;
    if (i < NN) { g_deg[i] = 1; g_cursor[i] = 0; }   // self-loop contributes 1
    if (i < NG * 128) g_pool[i] = 0.f;
    if (i < NG) g_cnt[i] = 0.f;
}

__global__ void k_count(const int* __restrict__ ei) {
    int e = blockIdx.x * blockDim.x + threadIdx.x;
    if (e < NE) {
        int d = clampi(load_idx(ei, NE + e, g_e64), NN);
        atomicAdd(&g_deg[d], 1);
    }
}

// ---- parallel scan: block partial sums -> scan partials -> write rowptr ----
__global__ void k_part() {                     // grid SCAN_NB, block SCAN_B
    __shared__ int red[SCAN_B];
    int t = threadIdx.x;
    int i = blockIdx.x * SCAN_B + t;
    red[t] = (i < NN) ? g_deg[i] : 0;
    __syncthreads();
#pragma unroll
    for (int off = SCAN_B / 2; off > 0; off >>= 1) {
        if (t < off) red[t] += red[t + off];
        __syncthreads();
    }
    if (t == 0) g_part[blockIdx.x] = red[0];
}

__global__ void k_scanpart() {                 // 1 block, 256 threads
    __shared__ int s[256];
    int t = threadIdx.x;
    int v = (t < SCAN_NB) ? g_part[t] : 0;
    s[t] = v;
    __syncthreads();
#pragma unroll
    for (int off = 1; off < 256; off <<= 1) {
        int x = (t >= off) ? s[t - off] : 0;
        __syncthreads();
        s[t] += x;
        __syncthreads();
    }
    if (t < SCAN_NB) g_partoff[t] = s[t] - v;  // exclusive
}

__global__ void k_write() {                    // grid SCAN_NB, block SCAN_B
    __shared__ int s[SCAN_B];
    int t = threadIdx.x;
    int i = blockIdx.x * SCAN_B + t;
    int v = (i < NN) ? g_deg[i] : 0;
    s[t] = v;
    __syncthreads();
#pragma unroll
    for (int off = 1; off < SCAN_B; off <<= 1) {
        int x = (t >= off) ? s[t - off] : 0;
        __syncthreads();
        s[t] += x;
        __syncthreads();
    }
    int base = g_partoff[blockIdx.x];
    if (i < NN) {
        g_rowptr[i] = base + s[t] - v;         // exclusive
        g_dinv[i]   = rsqrtf((float)v);
    }
    if (i == NN - 1) g_rowptr[NN] = base + s[t];
}

__global__ void k_fill(const int* __restrict__ ei) {
    int idx = blockIdx.x * blockDim.x + threadIdx.x;
    if (idx < NN) {
        int pos = g_rowptr[idx] + atomicAdd(&g_cursor[idx], 1);
        float di = g_dinv[idx];
        g_col[pos] = idx;
        g_wgt[pos] = di * di;
    } else if (idx < NTOT) {
        int e = idx - NN;
        int is64 = g_e64;
        int s = clampi(load_idx(ei, e, is64), NN);
        int d = clampi(load_idx(ei, NE + e, is64), NN);
        int pos = g_rowptr[d] + atomicAdd(&g_cursor[d], 1);
        g_col[pos] = s;
        g_wgt[pos] = g_dinv[s] * g_dinv[d];
    }
}

// ---------------------------------- SpMM -----------------------------------
template <int F, bool EPI, int IN, int OUT>
__global__ void k_spmm(const float* __restrict__ bias) {
    const float* __restrict__ hin  = scratch<IN>();
    float*       __restrict__ hout = scratch<OUT>();
    constexpr int VEC = F / 32;   // 2 or 4 floats per lane
    int warp = (blockIdx.x * blockDim.x + threadIdx.x) >> 5;
    int lane = threadIdx.x & 31;
    if (warp >= NN) return;
    int beg = g_rowptr[warp], end = g_rowptr[warp + 1];
    float acc[VEC];
#pragma unroll
    for (int v = 0; v < VEC; v++) acc[v] = 0.f;

    for (int k = beg; k < end; k++) {
        int   c  = g_col[k];
        float wt = g_wgt[k];
        const float* p = hin + (size_t)c * F + lane * VEC;
        if (VEC == 4) {
            float4 v = *(const float4*)p;
            acc[0] += wt * v.x; acc[1] += wt * v.y;
            acc[2] += wt * v.z; acc[3] += wt * v.w;
        } else {
            float2 v = *(const float2*)p;
            acc[0] += wt * v.x; acc[1] += wt * v.y;
        }
    }
    float* q = hout + (size_t)warp * F + lane * VEC;
    if (EPI) {
#pragma unroll
        for (int v = 0; v < VEC; v++) {
            acc[v] += bias[lane * VEC + v];
            acc[v] = fmaxf(acc[v], 0.f);
        }
    }
    if (VEC == 4) *(float4*)q = make_float4(acc[0], acc[1], acc[2], acc[3]);
    else          *(float2*)q = make_float2(acc[0], acc[1]);
}

// ---------------------------------- GEMM -----------------------------------
template <int K, int BN, bool EPI, int IN, int OUT>
__global__ void k_gemm(const float* __restrict__ Aext, const float* __restrict__ W,
                       const float* __restrict__ bias) {
    const float* __restrict__ A = (IN < 0) ? Aext : scratch<(IN < 0) ? 0 : IN>();
    float*       __restrict__ C = scratch<OUT>();
    constexpr int BM = 64, KT = 64;
    constexpr int TM = 4, TN = BN / 16;            // 4 or 8
    __shared__ float As[KT * BM];                  // transposed: As[k][m]
    __shared__ float Ws[KT * BN];                  // Ws[k][n]
    int tid = threadIdx.x;                         // 256 threads
    int tx = tid & 15;
    int ty = tid >> 4;
    int row0 = blockIdx.x * BM;

    float acc[TM][TN];
#pragma unroll
    for (int i = 0; i < TM; i++)
#pragma unroll
        for (int j = 0; j < TN; j++) acc[i][j] = 0.f;

    for (int kt = 0; kt < K; kt += KT) {
#pragma unroll
        for (int it = 0; it < (BM * KT / 4) / 256; it++) {
            int vi = tid + 256 * it;
            int m  = vi / (KT / 4);
            int kv = vi % (KT / 4);
            float4 v = make_float4(0.f, 0.f, 0.f, 0.f);
            int r = row0 + m;
            if (r < NN) v = *(const float4*)(A + (size_t)r * K + kt + kv * 4);
            As[(kv * 4 + 0) * BM + m] = v.x;
            As[(kv * 4 + 1) * BM + m] = v.y;
            As[(kv * 4 + 2) * BM + m] = v.z;
            As[(kv * 4 + 3) * BM + m] = v.w;
        }
#pragma unroll
        for (int it = 0; it < (KT * BN / 4) / 256; it++) {
            int vi = tid + 256 * it;
            int k  = vi / (BN / 4);
            int nv = vi % (BN / 4);
            *(float4*)&Ws[k * BN + nv * 4] =
                *(const float4*)(W + (size_t)(kt + k) * BN + nv * 4);
        }
        __syncthreads();
#pragma unroll
        for (int k = 0; k < KT; k++) {
            float4 av = *(const float4*)&As[k * BM + ty * TM];
            float a[TM] = {av.x, av.y, av.z, av.w};
            float w[TN];
#pragma unroll
            for (int jv = 0; jv < TN / 4; jv++) {
                float4 wv = *(const float4*)&Ws[k * BN + tx * TN + jv * 4];
                w[jv * 4 + 0] = wv.x; w[jv * 4 + 1] = wv.y;
                w[jv * 4 + 2] = wv.z; w[jv * 4 + 3] = wv.w;
            }
#pragma unroll
            for (int i = 0; i < TM; i++)
#pragma unroll
                for (int j = 0; j < TN; j++) acc[i][j] += a[i] * w[j];
        }
        __syncthreads();
    }
#pragma unroll
    for (int i = 0; i < TM; i++) {
        int r = row0 + ty * TM + i;
        if (r < NN) {
#pragma unroll
            for (int jv = 0; jv < TN / 4; jv++) {
                float4 v;
                float* pv = &acc[i][jv * 4];
                v.x = pv[0]; v.y = pv[1]; v.z = pv[2]; v.w = pv[3];
                if (EPI) {
                    int n = tx * TN + jv * 4;
                    v.x = fmaxf(v.x + bias[n + 0], 0.f);
                    v.y = fmaxf(v.y + bias[n + 1], 0.f);
                    v.z = fmaxf(v.z + bias[n + 2], 0.f);
                    v.w = fmaxf(v.w + bias[n + 3], 0.f);
                }
                *(float4*)(C + (size_t)r * BN + tx * TN + jv * 4) = v;
            }
        }
    }
}

// ------------------------------- mean pooling -------------------------------
__global__ void k_pool(const int* __restrict__ batch) {
    const float* __restrict__ h = g_bufC;
    constexpr int CH = 64;
    int n0 = blockIdx.x * CH;
    int t  = threadIdx.x;                 // 128 = feature
    if (n0 >= NN) return;
    int is64 = g_b64;
    int end = n0 + CH; if (end > NN) end = NN;
    float acc = 0.f, cacc = 0.f;
    int cur = clampi(load_idx(batch, n0, is64), NG);
    for (int n = n0; n < end; n++) {
        int g = clampi(load_idx(batch, n, is64), NG);
        if (g != cur) {
            atomicAdd(&g_pool[cur * 128 + t], acc);
            if (t == 0) atomicAdd(&g_cnt[cur], cacc);
            acc = 0.f; cacc = 0.f; cur = g;
        }
        acc  += h[(size_t)n * 128 + t];
        cacc += 1.f;
    }
    atomicAdd(&g_pool[cur * 128 + t], acc);
    if (t == 0) atomicAdd(&g_cnt[cur], cacc);
}

// --------------------------- classifier + log_softmax -----------------------
__global__ void k_cls(const float* __restrict__ Wc1, const float* __restrict__ bc1,
                      const float* __restrict__ Wc2, const float* __restrict__ bc2,
                      float* __restrict__ out) {
    int g = blockIdx.x;
    int t = threadIdx.x;                  // 128
    __shared__ float p[128];
    __shared__ float z[64];
    __shared__ float lo[OUTF];
    float c = fmaxf(g_cnt[g], 1.f);
    p[t] = g_pool[g * 128 + t] / c;
    __syncthreads();
    if (t < 64) {
        float a = bc1[t];
#pragma unroll 8
        for (int k = 0; k < 128; k++) a += p[k] * Wc1[k * 64 + t];
        z[t] = fmaxf(a, 0.f);
    }
    __syncthreads();
    if (t < OUTF) {
        float a = bc2[t];
#pragma unroll 8
        for (int k = 0; k < 64; k++) a += z[k] * Wc2[k * OUTF + t];
        lo[t] = a;
    }
    __syncthreads();
    if (t < OUTF) {
        float m = lo[0];
#pragma unroll
        for (int i = 1; i < OUTF; i++) m = fmaxf(m, lo[i]);
        float s = 0.f;
#pragma unroll
        for (int i = 0; i < OUTF; i++) s += expf(lo[i] - m);
        out[g * OUTF + t] = lo[t] - m - logf(s);
    }
}

// --------------------------------- launch -----------------------------------
extern "C" void kernel_launch(void* const* d_in, const int* in_sizes, int n_in,
                              void* d_out, int out_size) {
    const float* x     = (const float*)d_in[0];
    const int*   ei    = (const int*)d_in[1];
    const int*   batch = (const int*)d_in[2];
    const float* W1  = (const float*)d_in[3];
    const float* b1  = (const float*)d_in[4];
    const float* W2  = (const float*)d_in[5];
    const float* b2  = (const float*)d_in[6];
    const float* W3  = (const float*)d_in[7];
    const float* b3  = (const float*)d_in[8];
    const float* Wc1 = (const float*)d_in[9];
    const float* bc1 = (const float*)d_in[10];
    const float* Wc2 = (const float*)d_in[11];
    const float* bc2 = (const float*)d_in[12];
    float* out = (float*)d_out;

    const int GB = (NN + 63) / 64;          // gemm blocks
    const int SP = (NN + 3) / 4;            // spmm blocks (4 warps/block)

    k_detect  <<<1, 128>>>(ei, batch);
    k_init    <<<(NN + 255) / 256, 256>>>();
    k_count   <<<(NE + 255) / 256, 256>>>(ei);
    k_part    <<<SCAN_NB, SCAN_B>>>();
    k_scanpart<<<1, 256>>>();
    k_write   <<<SCAN_NB, SCAN_B>>>();
    k_fill    <<<(NTOT + 255) / 256, 256>>>(ei);

    // buffers: 0=A(64w) 1=B(64w) 2=C(128w) 3=D(128w)
    // L1: t0 = x @ W1 -> A ; h1 = relu(CSR·A + b1) -> B
    k_gemm<128, 64, false, -1, 0><<<GB, 256>>>(x, W1, nullptr);
    k_spmm<64, true, 0, 1>       <<<SP, 128>>>(b1);
    // L2: s2 = CSR·B -> A ; h2 = relu(A @ W2 + b2) -> C
    k_spmm<64, false, 1, 0>      <<<SP, 128>>>(nullptr);
    k_gemm<64, 128, true, 0, 2>  <<<GB, 256>>>(nullptr, W2, b2);
    // L3: t3 = C @ W3 -> D ; h3 = relu(CSR·D + b3) -> C
    k_gemm<128, 128, false, 2, 3><<<GB, 256>>>(nullptr, W3, nullptr);
    k_spmm<128, true, 3, 2>      <<<SP, 128>>>(b3);

    k_pool<<<(NN + 63) / 64, 128>>>(batch);
    k_cls <<<NG, 128>>>(Wc1, bc1, Wc2, bc2, out);
}

// round 9
// speedup vs baseline: 1.5498x; 1.2023x over previous
#include <cuda_runtime.h>
#include <cuda_bf16.h>
#include <math.h>

// ---------------------------------------------------------------------------
// GCN_Protein: 3x GCNConv -> mean pool -> MLP -> log_softmax
//   R5: GEMM retiled to 128xBN (8xTN reg tiles, KT=32);
//       SpMM edges packed into int2{col,wgt} + 2x unrolled gathers;
//       GEMM1 moved to launch slot 3 (ncu capture slot) for next-round data.
// ---------------------------------------------------------------------------

#define NN 100000
#define NE 1600000
#define NTOT (NN + NE)
#define NG 512
#define OUTF 10

#define SCAN_B 512
#define SCAN_NB ((NN + SCAN_B - 1) / SCAN_B)   // 196

// ------------------------- scratch (device globals) ------------------------
__device__ int   g_e64;
__device__ int   g_b64;
__device__ int   g_deg[NN];
__device__ int   g_rowptr[NN + 1];
__device__ int   g_cursor[NN];
__device__ float g_dinv[NN];
__device__ int   g_part[SCAN_NB];
__device__ int   g_partoff[SCAN_NB];
__device__ int2  g_colw[NTOT];               // packed {col, float_as_int(wgt)}
__device__ float g_bufA[(size_t)NN * 64];
__device__ float g_bufB[(size_t)NN * 64];
__device__ float g_bufC[(size_t)NN * 128];
__device__ float g_bufD[(size_t)NN * 128];
__device__ float g_pool[NG * 128];
__device__ float g_cnt[NG];

template <int ID>
__device__ __forceinline__ float* scratch() {
    if (ID == 0) return g_bufA;
    if (ID == 1) return g_bufB;
    if (ID == 2) return g_bufC;
    return g_bufD;
}

__device__ __forceinline__ int clampi(int v, int hi) {
    return v < 0 ? 0 : (v >= hi ? hi - 1 : v);
}

__device__ __forceinline__ int load_idx(const int* __restrict__ p, int i, int is64) {
    return is64 ? p[2 * i] : p[i];
}

// ------------------------------ dtype detection ------------------------------
__global__ void k_detect(const int* __restrict__ ei, const int* __restrict__ batch) {
    __shared__ int nz_e, nz_b;
    int t = threadIdx.x;                       // 128 threads
    if (t == 0) { nz_e = 0; nz_b = 0; }
    __syncthreads();
    long long stride = (2LL * NE) / 128;
    int we = (int)((long long)t * stride) | 1;
    if (ei[we] != 0) atomicAdd(&nz_e, 1);
    int wb = (NN - 1 - 2 * t) | 1;
    if (batch[wb] != 0) atomicAdd(&nz_b, 1);
    __syncthreads();
    if (t == 0) { g_e64 = (nz_e == 0); g_b64 = (nz_b == 0); }
}

// ------------------------------ preprocessing ------------------------------
__global__ void k_init() {
    int i = blockIdx.x * blockDim.x + threadIdx.x;
    if (i < NN) { g_deg[i] = 1; g_cursor[i] = 0; }   // self-loop contributes 1
    if (i < NG * 128) g_pool[i] = 0.f;
    if (i < NG) g_cnt[i] = 0.f;
}

__global__ void k_count(const int* __restrict__ ei) {
    int e = blockIdx.x * blockDim.x + threadIdx.x;
    if (e < NE) {
        int d = clampi(load_idx(ei, NE + e, g_e64), NN);
        atomicAdd(&g_deg[d], 1);
    }
}

// ---- parallel scan: block partials -> scan partials -> write rowptr ----
__global__ void k_part() {
    __shared__ int red[SCAN_B];
    int t = threadIdx.x;
    int i = blockIdx.x * SCAN_B + t;
    red[t] = (i < NN) ? g_deg[i] : 0;
    __syncthreads();
#pragma unroll
    for (int off = SCAN_B / 2; off > 0; off >>= 1) {
        if (t < off) red[t] += red[t + off];
        __syncthreads();
    }
    if (t == 0) g_part[blockIdx.x] = red[0];
}

__global__ void k_scanpart() {
    __shared__ int s[256];
    int t = threadIdx.x;
    int v = (t < SCAN_NB) ? g_part[t] : 0;
    s[t] = v;
    __syncthreads();
#pragma unroll
    for (int off = 1; off < 256; off <<= 1) {
        int x = (t >= off) ? s[t - off] : 0;
        __syncthreads();
        s[t] += x;
        __syncthreads();
    }
    if (t < SCAN_NB) g_partoff[t] = s[t] - v;  // exclusive
}

__global__ void k_write() {
    __shared__ int s[SCAN_B];
    int t = threadIdx.x;
    int i = blockIdx.x * SCAN_B + t;
    int v = (i < NN) ? g_deg[i] : 0;
    s[t] = v;
    __syncthreads();
#pragma unroll
    for (int off = 1; off < SCAN_B; off <<= 1) {
        int x = (t >= off) ? s[t - off] : 0;
        __syncthreads();
        s[t] += x;
        __syncthreads();
    }
    int base = g_partoff[blockIdx.x];
    if (i < NN) {
        g_rowptr[i] = base + s[t] - v;         // exclusive
        g_dinv[i]   = rsqrtf((float)v);
    }
    if (i == NN - 1) g_rowptr[NN] = base + s[t];
}

__global__ void k_fill(const int* __restrict__ ei) {
    int idx = blockIdx.x * blockDim.x + threadIdx.x;
    if (idx < NN) {
        int pos = g_rowptr[idx] + atomicAdd(&g_cursor[idx], 1);
        float di = g_dinv[idx];
        g_colw[pos] = make_int2(idx, __float_as_int(di * di));
    } else if (idx < NTOT) {
        int e = idx - NN;
        int is64 = g_e64;
        int s = clampi(load_idx(ei, e, is64), NN);
        int d = clampi(load_idx(ei, NE + e, is64), NN);
        int pos = g_rowptr[d] + atomicAdd(&g_cursor[d], 1);
        g_colw[pos] = make_int2(s, __float_as_int(g_dinv[s] * g_dinv[d]));
    }
}

// ---------------------------------- SpMM -----------------------------------
// warp-per-node, packed int2 edge records, 2x-unrolled gathers.
template <int F, bool EPI, int IN, int OUT>
__global__ void k_spmm(const float* __restrict__ bias) {
    const float* __restrict__ hin  = scratch<IN>();
    float*       __restrict__ hout = scratch<OUT>();
    constexpr int VEC = F / 32;   // 2 or 4 floats per lane
    int warp = (blockIdx.x * blockDim.x + threadIdx.x) >> 5;
    int lane = threadIdx.x & 31;
    if (warp >= NN) return;
    int beg = g_rowptr[warp], end = g_rowptr[warp + 1];
    float acc[VEC];
#pragma unroll
    for (int v = 0; v < VEC; v++) acc[v] = 0.f;

    int k = beg;
    for (; k + 2 <= end; k += 2) {
        int2 e0 = g_colw[k];
        int2 e1 = g_colw[k + 1];
        float w0 = __int_as_float(e0.y);
        float w1 = __int_as_float(e1.y);
        const float* p0 = hin + (size_t)e0.x * F + lane * VEC;
        const float* p1 = hin + (size_t)e1.x * F + lane * VEC;
        if (VEC == 4) {
            float4 v0 = *(const float4*)p0;
            float4 v1 = *(const float4*)p1;
            acc[0] += w0 * v0.x; acc[1] += w0 * v0.y;
            acc[2] += w0 * v0.z; acc[3] += w0 * v0.w;
            acc[0] += w1 * v1.x; acc[1] += w1 * v1.y;
            acc[2] += w1 * v1.z; acc[3] += w1 * v1.w;
        } else {
            float2 v0 = *(const float2*)p0;
            float2 v1 = *(const float2*)p1;
            acc[0] += w0 * v0.x; acc[1] += w0 * v0.y;
            acc[0] += w1 * v1.x; acc[1] += w1 * v1.y;
        }
    }
    if (k < end) {
        int2 e0 = g_colw[k];
        float w0 = __int_as_float(e0.y);
        const float* p0 = hin + (size_t)e0.x * F + lane * VEC;
        if (VEC == 4) {
            float4 v0 = *(const float4*)p0;
            acc[0] += w0 * v0.x; acc[1] += w0 * v0.y;
            acc[2] += w0 * v0.z; acc[3] += w0 * v0.w;
        } else {
            float2 v0 = *(const float2*)p0;
            acc[0] += w0 * v0.x; acc[1] += w0 * v0.y;
        }
    }

    float* q = hout + (size_t)warp * F + lane * VEC;
    if (EPI) {
#pragma unroll
        for (int v = 0; v < VEC; v++) {
            acc[v] += bias[lane * VEC + v];
            acc[v] = fmaxf(acc[v], 0.f);
        }
    }
    if (VEC == 4) *(float4*)q = make_float4(acc[0], acc[1], acc[2], acc[3]);
    else          *(float2*)q = make_float2(acc[0], acc[1]);
}

// ---------------------------------- GEMM -----------------------------------
// C[N, BN] = A[N, K] @ W[K, BN] (+bias, relu). BM=128, KT=32, 256 thr, TM=8.
template <int K, int BN, bool EPI, int IN, int OUT>
__global__ void k_gemm(const float* __restrict__ Aext, const float* __restrict__ W,
                       const float* __restrict__ bias) {
    const float* __restrict__ A = (IN < 0) ? Aext : scratch<(IN < 0) ? 0 : IN>();
    float*       __restrict__ C = scratch<OUT>();
    constexpr int BM = 128, KT = 32;
    constexpr int TM = 8, TN = BN / 16;            // TN = 4 or 8
    __shared__ float As[KT * BM];                  // transposed: As[k][m]
    __shared__ float Ws[KT * BN];                  // Ws[k][n]
    int tid = threadIdx.x;                         // 256 threads
    int tx = tid & 15;                             // n-dir
    int ty = tid >> 4;                             // m-dir
    int row0 = blockIdx.x * BM;

    float acc[TM][TN];
#pragma unroll
    for (int i = 0; i < TM; i++)
#pragma unroll
        for (int j = 0; j < TN; j++) acc[i][j] = 0.f;

    for (int kt = 0; kt < K; kt += KT) {
        // A tile: BM*KT/4 = 1024 float4, 4 per thread, transposed into smem
#pragma unroll
        for (int it = 0; it < 4; it++) {
            int vi = tid + 256 * it;
            int m  = vi >> 3;                      // / (KT/4)
            int kv = vi & 7;
            float4 v = make_float4(0.f, 0.f, 0.f, 0.f);
            int r = row0 + m;
            if (r < NN) v = *(const float4*)(A + (size_t)r * K + kt + kv * 4);
            As[(kv * 4 + 0) * BM + m] = v.x;
            As[(kv * 4 + 1) * BM + m] = v.y;
            As[(kv * 4 + 2) * BM + m] = v.z;
            As[(kv * 4 + 3) * BM + m] = v.w;
        }
        // W tile: KT*BN/4 float4
#pragma unroll
        for (int it = 0; it < (KT * BN / 4) / 256; it++) {
            int vi = tid + 256 * it;
            int k  = vi / (BN / 4);
            int nv = vi % (BN / 4);
            *(float4*)&Ws[k * BN + nv * 4] =
                *(const float4*)(W + (size_t)(kt + k) * BN + nv * 4);
        }
        __syncthreads();
#pragma unroll
        for (int k = 0; k < KT; k++) {
            float a[TM];
#pragma unroll
            for (int iv = 0; iv < TM / 4; iv++) {
                float4 av = *(const float4*)&As[k * BM + ty * TM + iv * 4];
                a[iv * 4 + 0] = av.x; a[iv * 4 + 1] = av.y;
                a[iv * 4 + 2] = av.z; a[iv * 4 + 3] = av.w;
            }
            float w[TN];
#pragma unroll
            for (int jv = 0; jv < TN / 4; jv++) {
                float4 wv = *(const float4*)&Ws[k * BN + tx * TN + jv * 4];
                w[jv * 4 + 0] = wv.x; w[jv * 4 + 1] = wv.y;
                w[jv * 4 + 2] = wv.z; w[jv * 4 + 3] = wv.w;
            }
#pragma unroll
            for (int i = 0; i < TM; i++)
#pragma unroll
                for (int j = 0; j < TN; j++) acc[i][j] += a[i] * w[j];
        }
        __syncthreads();
    }
#pragma unroll
    for (int i = 0; i < TM; i++) {
        int r = row0 + ty * TM + i;
        if (r < NN) {
#pragma unroll
            for (int jv = 0; jv < TN / 4; jv++) {
                float4 v;
                float* pv = &acc[i][jv * 4];
                v.x = pv[0]; v.y = pv[1]; v.z = pv[2]; v.w = pv[3];
                if (EPI) {
                    int n = tx * TN + jv * 4;
                    v.x = fmaxf(v.x + bias[n + 0], 0.f);
                    v.y = fmaxf(v.y + bias[n + 1], 0.f);
                    v.z = fmaxf(v.z + bias[n + 2], 0.f);
                    v.w = fmaxf(v.w + bias[n + 3], 0.f);
                }
                *(float4*)(C + (size_t)r * BN + tx * TN + jv * 4) = v;
            }
        }
    }
}

// ------------------------------- mean pooling -------------------------------
__global__ void k_pool(const int* __restrict__ batch) {
    const float* __restrict__ h = g_bufC;
    constexpr int CH = 64;
    int n0 = blockIdx.x * CH;
    int t  = threadIdx.x;                 // 128 = feature
    if (n0 >= NN) return;
    int is64 = g_b64;
    int end = n0 + CH; if (end > NN) end = NN;
    float acc = 0.f, cacc = 0.f;
    int cur = clampi(load_idx(batch, n0, is64), NG);
    for (int n = n0; n < end; n++) {
        int g = clampi(load_idx(batch, n, is64), NG);
        if (g != cur) {
            atomicAdd(&g_pool[cur * 128 + t], acc);
            if (t == 0) atomicAdd(&g_cnt[cur], cacc);
            acc = 0.f; cacc = 0.f; cur = g;
        }
        acc  += h[(size_t)n * 128 + t];
        cacc += 1.f;
    }
    atomicAdd(&g_pool[cur * 128 + t], acc);
    if (t == 0) atomicAdd(&g_cnt[cur], cacc);
}

// --------------------------- classifier + log_softmax -----------------------
__global__ void k_cls(const float* __restrict__ Wc1, const float* __restrict__ bc1,
                      const float* __restrict__ Wc2, const float* __restrict__ bc2,
                      float* __restrict__ out) {
    int g = blockIdx.x;
    int t = threadIdx.x;                  // 128
    __shared__ float p[128];
    __shared__ float z[64];
    __shared__ float lo[OUTF];
    float c = fmaxf(g_cnt[g], 1.f);
    p[t] = g_pool[g * 128 + t] / c;
    __syncthreads();
    if (t < 64) {
        float a = bc1[t];
#pragma unroll 8
        for (int k = 0; k < 128; k++) a += p[k] * Wc1[k * 64 + t];
        z[t] = fmaxf(a, 0.f);
    }
    __syncthreads();
    if (t < OUTF) {
        float a = bc2[t];
#pragma unroll 8
        for (int k = 0; k < 64; k++) a += z[k] * Wc2[k * OUTF + t];
        lo[t] = a;
    }
    __syncthreads();
    if (t < OUTF) {
        float m = lo[0];
#pragma unroll
        for (int i = 1; i < OUTF; i++) m = fmaxf(m, lo[i]);
        float s = 0.f;
#pragma unroll
        for (int i = 0; i < OUTF; i++) s += expf(lo[i] - m);
        out[g * OUTF + t] = lo[t] - m - logf(s);
    }
}

// --------------------------------- launch -----------------------------------
extern "C" void kernel_launch(void* const* d_in, const int* in_sizes, int n_in,
                              void* d_out, int out_size) {
    const float* x     = (const float*)d_in[0];
    const int*   ei    = (const int*)d_in[1];
    const int*   batch = (const int*)d_in[2];
    const float* W1  = (const float*)d_in[3];
    const float* b1  = (const float*)d_in[4];
    const float* W2  = (const float*)d_in[5];
    const float* b2  = (const float*)d_in[6];
    const float* W3  = (const float*)d_in[7];
    const float* b3  = (const float*)d_in[8];
    const float* Wc1 = (const float*)d_in[9];
    const float* bc1 = (const float*)d_in[10];
    const float* Wc2 = (const float*)d_in[11];
    const float* bc2 = (const float*)d_in[12];
    float* out = (float*)d_out;

    const int GB = (NN + 127) / 128;        // gemm blocks (BM=128)
    const int SP = (NN + 3) / 4;            // spmm blocks (4 warps/block)

    k_detect  <<<1, 128>>>(ei, batch);
    k_init    <<<(NN + 255) / 256, 256>>>();
    k_count   <<<(NE + 255) / 256, 256>>>(ei);
    // GEMM1 has no CSR dependency; placed at launch slot 3 (= ncu capture slot)
    k_gemm<128, 64, false, -1, 0><<<GB, 256>>>(x, W1, nullptr);
    k_part    <<<SCAN_NB, SCAN_B>>>();
    k_scanpart<<<1, 256>>>();
    k_write   <<<SCAN_NB, SCAN_B>>>();
    k_fill    <<<(NTOT + 255) / 256, 256>>>(ei);

    // buffers: 0=A(64w) 1=B(64w) 2=C(128w) 3=D(128w)
    // L1: h1 = relu(CSR·A + b1) -> B
    k_spmm<64, true, 0, 1>       <<<SP, 128>>>(b1);
    // L2: s2 = CSR·B -> A ; h2 = relu(A @ W2 + b2) -> C
    k_spmm<64, false, 1, 0>      <<<SP, 128>>>(nullptr);
    k_gemm<64, 128, true, 0, 2>  <<<GB, 256>>>(nullptr, W2, b2);
    // L3: t3 = C @ W3 -> D ; h3 = relu(CSR·D + b3) -> C
    k_gemm<128, 128, false, 2, 3><<<GB, 256>>>(nullptr, W3, nullptr);
    k_spmm<128, true, 3, 2>      <<<SP, 128>>>(b3);

    k_pool<<<(NN + 63) / 64, 128>>>(batch);
    k_cls <<<NG, 128>>>(Wc1, bc1, Wc2, bc2, out);
}